// round 12
// baseline (speedup 1.0000x reference)
#include <cuda_runtime.h>
#include <cuda_bf16.h>
#include <cstdint>
#include <math.h>

#define Bk 32
#define Tk 400
#define Pk 3500
#define Sk 2000
#define Ek 50000
#define NCH 500
#define CHSZ 100
#define NTILEH 220             // 110 p-tiles x 2 batch halves
#define NUNIT (Sk + NTILEH)    // 2220 classic work units (init + fallback)
#define NSTB (Sk / 16)         // 125 state blocks
#define NUNIT2 (2 * Sk + NTILEH) // 4220 split work units
#define KNORM 8
#define MAXBLK 256
#define ARCCAP 4224            // records fitting in the 33KB smem union

// ------------- device-global scratch (static, no runtime allocation) -------------
__device__ float d_alpha[2][Sk * Bk];
__device__ float d_ex[2][Pk * Bk];
__device__ float d_part[MAXBLK * Bk];
__device__ uint2 d_arcs[Ek];              // {src | pdf<<16, prob_bits}, dst-sorted
__device__ int   d_hist[Sk * NCH];        // transposed: [state][chunk]
__device__ int   d_base[Sk + 1];
__device__ int   d_totals[Sk];
__device__ unsigned d_bcount;             // 0 at rest
__device__ unsigned d_bgen;

// ============ grid barrier: single atomic counter, acquire/release (PROVEN) ======
__device__ __forceinline__ void gbar(unsigned& g, int nblk, int tid) {
    __syncthreads();
    if (tid == 0) {
        unsigned gn = g + 1u;
        unsigned a;
        asm volatile("atom.add.release.gpu.u32 %0, [%1], %2;"
                     : "=r"(a) : "l"(&d_bcount), "r"(1u) : "memory");
        if (a == (unsigned)nblk - 1u) {
            asm volatile("st.relaxed.gpu.u32 [%0], %1;"
                         :: "l"(&d_bcount), "r"(0u) : "memory");
            asm volatile("st.release.gpu.u32 [%0], %1;"
                         :: "l"(&d_bgen), "r"(gn) : "memory");
        } else {
            unsigned cur;
            int spins = 0;
            while (true) {
                asm volatile("ld.acquire.gpu.u32 %0, [%1];"
                             : "=r"(cur) : "l"(&d_bgen) : "memory");
                if (cur == gn) break;
                if (++spins > 128) __nanosleep(40);   // pure spin first: fast wakeup
            }
        }
    }
    __syncthreads();
    g = g + 1u;
}

// ================= setup: deterministic stable counting sort by dst ==============
__global__ void k_hist(const int* __restrict__ dst) {
    __shared__ int cnt[Sk];
    int c = blockIdx.x;
    for (int s = threadIdx.x; s < Sk; s += blockDim.x) cnt[s] = 0;
    __syncthreads();
    int e0 = c * CHSZ, e1 = min(Ek, e0 + CHSZ);
    for (int e = e0 + threadIdx.x; e < e1; e += blockDim.x) atomicAdd(&cnt[dst[e]], 1);
    __syncthreads();
    for (int s = threadIdx.x; s < Sk; s += blockDim.x) d_hist[s * NCH + c] = cnt[s];
}

// totals + scan + offsets fused into one persistent kernel (2 internal barriers)
__global__ __launch_bounds__(256, 1) void k_mid(int nblk) {
    const int tid = threadIdx.x, wid = tid >> 5, lane = tid & 31, blk = blockIdx.x;
    const int gw = blk * 8 + wid;
    const int NWRP = nblk * 8;
    unsigned g;
    asm volatile("ld.relaxed.gpu.u32 %0, [%1];" : "=r"(g) : "l"(&d_bgen) : "memory");

    for (int s = gw; s < Sk; s += NWRP) {
        int sum = 0;
        for (int c = lane; c < NCH; c += 32) sum += d_hist[s * NCH + c];
        #pragma unroll
        for (int off = 16; off; off >>= 1) sum += __shfl_down_sync(0xFFFFFFFFu, sum, off);
        if (lane == 0) d_totals[s] = sum;
    }
    gbar(g, nblk, tid);

    if (blk == 0) {
        __shared__ int ssum[256];
        int vals[8];
        int ts = 0;
        if (tid < Sk / 8) {
            #pragma unroll
            for (int j = 0; j < 8; j++) { vals[j] = d_totals[tid * 8 + j]; ts += vals[j]; }
        }
        ssum[tid] = ts;
        __syncthreads();
        for (int d = 1; d < 256; d <<= 1) {
            int v = ssum[tid];
            int u = (tid >= d) ? ssum[tid - d] : 0;
            __syncthreads();
            ssum[tid] = v + u;
            __syncthreads();
        }
        int pre = tid ? ssum[tid - 1] : 0;
        if (tid < Sk / 8) {
            int run = pre;
            #pragma unroll
            for (int j = 0; j < 8; j++) { d_base[tid * 8 + j] = run; run += vals[j]; }
        }
        if (tid == 255) d_base[Sk] = ssum[255];
    }
    gbar(g, nblk, tid);

    for (int s = gw; s < Sk; s += NWRP) {
        int run = d_base[s];
        for (int c0 = 0; c0 < NCH; c0 += 32) {
            int c = c0 + lane;
            int h = (c < NCH) ? d_hist[s * NCH + c] : 0;
            int inc = h;
            #pragma unroll
            for (int d = 1; d < 32; d <<= 1) {
                int n = __shfl_up_sync(0xFFFFFFFFu, inc, d);
                if (lane >= d) inc += n;
            }
            if (c < NCH) d_hist[s * NCH + c] = run + inc - h;
            run += __shfl_sync(0xFFFFFFFFu, inc, 31);
        }
    }
}

__global__ void k_scatter(const int* __restrict__ src, const int* __restrict__ dst,
                          const int* __restrict__ pdf, const float* __restrict__ ltp) {
    __shared__ int offs[Sk];
    __shared__ int sdst[CHSZ];
    __shared__ uint2 srec[CHSZ];
    int c = blockIdx.x;
    for (int s = threadIdx.x; s < Sk; s += blockDim.x) offs[s] = d_hist[s * NCH + c];
    int e0 = c * CHSZ, e1 = min(Ek, e0 + CHSZ), n = e1 - e0;
    for (int i = threadIdx.x; i < n; i += blockDim.x) {
        int e = e0 + i;
        sdst[i] = dst[e];
        srec[i] = make_uint2((unsigned)src[e] | ((unsigned)pdf[e] << 16),
                             __float_as_uint(expf(ltp[e])));
    }
    __syncthreads();
    if (threadIdx.x == 0) {
        for (int i = 0; i < n; i++) {
            int d = sdst[i];
            d_arcs[offs[d]++] = srec[i];
        }
    }
}

// exp(x) transpose half-tile with 8-row staging (fits 32 warps/block in smem)
// half-tile = p rows [32j,32j+32) x batch rows [16h,16h+16)
__device__ __forceinline__ void ex_tile(int j, int h, int t, int buf,
                                        const float* __restrict__ x,
                                        float* tw, int lane) {
    int p0 = j * 32;
    int p = p0 + lane;
    bool pok = (p < Pk);
    #pragma unroll
    for (int q = 0; q < 2; q++) {
        int base_b = 16 * h + 8 * q;
        #pragma unroll
        for (int bb = 0; bb < 8; bb++) {
            float v = pok ? x[(base_b + bb) * (Tk * Pk) + t * Pk + p] : 0.0f;
            tw[bb * 33 + lane] = v;
        }
        __syncwarp();
        int b2 = lane & 7, pr = lane >> 3;
        #pragma unroll
        for (int k = 0; k < 8; k++) {
            int pp = k * 4 + pr;
            int pg = p0 + pp;
            if (pg < Pk)
                d_ex[buf][pg * 32 + base_b + b2] = __expf(tw[b2 * 33 + pp]);
        }
        __syncwarp();
    }
}

// arc gather pass: templated so smem vs global record pointers each specialize
template <typename AP>
__device__ __forceinline__ float arc_pass(AP ap, int b0, int b1,
                                          const float* __restrict__ aC,
                                          const float* __restrict__ eC, int lane) {
    float a0 = 0.f, a1 = 0.f, a2 = 0.f, a3 = 0.f;
    int i = b0;
    for (; i + 8 <= b1; i += 8) {
        uint2 r0 = ap[i],     r1 = ap[i + 1], r2 = ap[i + 2], r3 = ap[i + 3];
        uint2 r4 = ap[i + 4], r5 = ap[i + 5], r6 = ap[i + 6], r7 = ap[i + 7];
        float g0 = __ldcg(&aC[(r0.x & 0xFFFF) * 32 + lane]) * __ldcg(&eC[(r0.x >> 16) * 32 + lane]);
        float g1 = __ldcg(&aC[(r1.x & 0xFFFF) * 32 + lane]) * __ldcg(&eC[(r1.x >> 16) * 32 + lane]);
        float g2 = __ldcg(&aC[(r2.x & 0xFFFF) * 32 + lane]) * __ldcg(&eC[(r2.x >> 16) * 32 + lane]);
        float g3 = __ldcg(&aC[(r3.x & 0xFFFF) * 32 + lane]) * __ldcg(&eC[(r3.x >> 16) * 32 + lane]);
        float g4 = __ldcg(&aC[(r4.x & 0xFFFF) * 32 + lane]) * __ldcg(&eC[(r4.x >> 16) * 32 + lane]);
        float g5 = __ldcg(&aC[(r5.x & 0xFFFF) * 32 + lane]) * __ldcg(&eC[(r5.x >> 16) * 32 + lane]);
        float g6 = __ldcg(&aC[(r6.x & 0xFFFF) * 32 + lane]) * __ldcg(&eC[(r6.x >> 16) * 32 + lane]);
        float g7 = __ldcg(&aC[(r7.x & 0xFFFF) * 32 + lane]) * __ldcg(&eC[(r7.x >> 16) * 32 + lane]);
        a0 += __uint_as_float(r0.y) * g0;  a1 += __uint_as_float(r1.y) * g1;
        a2 += __uint_as_float(r2.y) * g2;  a3 += __uint_as_float(r3.y) * g3;
        a0 += __uint_as_float(r4.y) * g4;  a1 += __uint_as_float(r5.y) * g5;
        a2 += __uint_as_float(r6.y) * g6;  a3 += __uint_as_float(r7.y) * g7;
    }
    for (; i + 2 <= b1; i += 2) {
        uint2 r0 = ap[i], r1 = ap[i + 1];
        a0 += __uint_as_float(r0.y) *
              (__ldcg(&aC[(r0.x & 0xFFFF) * 32 + lane]) * __ldcg(&eC[(r0.x >> 16) * 32 + lane]));
        a1 += __uint_as_float(r1.y) *
              (__ldcg(&aC[(r1.x & 0xFFFF) * 32 + lane]) * __ldcg(&eC[(r1.x >> 16) * 32 + lane]));
    }
    if (i < b1) {
        uint2 r0 = ap[i];
        a0 += __uint_as_float(r0.y) *
              (__ldcg(&aC[(r0.x & 0xFFFF) * 32 + lane]) * __ldcg(&eC[(r0.x >> 16) * 32 + lane]));
    }
    return (a0 + a1) + (a2 + a3);
}

// ============================ persistent main kernel =============================
// 1024 threads = 32 warps/block. Simple layout (nblk >= 132):
//   blocks 0..124  : 16 states each, TWO warps per state (split arc list)
//   blocks 125..131: 220 ex half-tile warps
//   blocks 132+    : idle (barrier only)
__global__ __launch_bounds__(1024, 1) void k_main(const float* __restrict__ x,
                                                  const float* __restrict__ initlp,
                                                  float* __restrict__ out, int nblk) {
    __shared__ float s_part[32 * 32];
    __shared__ float s_half[32 * 32];
    __shared__ float s_scale[32];
    __shared__ __align__(16) float s_mem[8448];   // union: arc cache OR 32x(8x33) tiles

    const int tid = threadIdx.x, wid = tid >> 5, lane = tid & 31, blk = blockIdx.x;
    const int NW2 = nblk * 32;
    const int W = blk * 32 + wid;
    float* tw = s_mem + wid * 264;                // 8x33 staging per warp
    uint2* s_arcs = (uint2*)s_mem;

    unsigned g;
    asm volatile("ld.relaxed.gpu.u32 %0, [%1];" : "=r"(g) : "l"(&d_bgen) : "memory");

    const bool simple  = (NW2 >= NUNIT2);
    const bool stateBlk = simple && (blk < NSTB);
    const int  tileW    = simple ? ((blk - NSTB) * 32 + wid) : -1;  // valid if in [0,220)
    const bool isTile   = simple && blk >= NSTB && tileW < NTILEH;
    const int  npart    = simple ? NSTB : nblk;

    // ---- init: alpha0 and ex slice for t=0 (uses tw; before arc staging) ----
    for (int u = W; u < NUNIT; u += NW2) {
        if (u < Sk) d_alpha[0][u * 32 + lane] = __expf(initlp[u]);
        else        ex_tile((u - Sk) >> 1, (u - Sk) & 1, 0, 0, x, tw, lane);
    }
    __syncthreads();

    // ---- stage this block's arc records into smem; compute per-warp half bounds --
    bool staged = false;
    int h0 = 0, h1 = 0;
    if (stateBlk) {
        int gbase0 = d_base[blk * 16];
        int gend   = d_base[blk * 16 + 16];
        int nA = gend - gbase0;
        int s = blk * 16 + (wid >> 1);
        int b0, b1;
        if (nA <= ARCCAP) {
            for (int i = tid; i < nA; i += 1024) s_arcs[i] = d_arcs[gbase0 + i];
            staged = true;
            b0 = d_base[s] - gbase0;
            b1 = d_base[s + 1] - gbase0;
        } else {
            b0 = d_base[s];
            b1 = d_base[s + 1];
        }
        int mid = b0 + ((b1 - b0 + 1) >> 1);
        if (wid & 1) { h0 = mid; h1 = b1; }
        else         { h0 = b0;  h1 = mid; }
    }
    double logC = 0.0;
    gbar(g, nblk, tid);

    int cur = 0;
    for (int t = 0; t < Tk; t++) {
        const bool ev = (t % KNORM == 0) && (t > 0);
        const bool mkpart = ((t + 1) % KNORM == 0);

        if (stateBlk && ev) {
            float c = 0.0f;
            for (int r = wid; r < npart; r += 32)
                c += __ldcg(&d_part[r * 32 + lane]);
            s_part[wid * 32 + lane] = c;
            __syncthreads();
            if (wid == 0) {
                float cs = 0.0f;
                #pragma unroll
                for (int k = 0; k < 32; k++) cs += s_part[k * 32 + lane];
                s_scale[lane] = (cs > 0.0f) ? (1.0f / cs) : 1.0f;
                if (blk == 0 && cs > 0.0f) logC += log((double)cs);
            }
            __syncthreads();
        }

        const float* aC = d_alpha[cur];
        float*       aN = d_alpha[cur ^ 1];
        const float* eC = d_ex[t & 1];
        float psum = 0.0f;

        if (simple) {
            if (stateBlk) {
                float vh = staged ? arc_pass(s_arcs, h0, h1, aC, eC, lane)
                                  : arc_pass((const uint2*)d_arcs, h0, h1, aC, eC, lane);
                s_half[wid * 32 + lane] = vh;
            } else if (isTile && t + 1 < Tk) {
                ex_tile(tileW >> 1, tileW & 1, t + 1, (t + 1) & 1, x, tw, lane);
            }
            __syncthreads();
            if (stateBlk && !(wid & 1)) {
                const float sc = ev ? s_scale[lane] : 1.0f;
                int s = blk * 16 + (wid >> 1);
                float v = sc * (s_half[wid * 32 + lane] + s_half[wid * 32 + 32 + lane]);
                aN[s * 32 + lane] = v;
                psum = v;
            }
        } else {
            // fallback: classic one-warp-per-state layout (never taken on 148-SM part)
            const float sc = ev ? s_scale[lane] : 1.0f;
            for (int u = W; u < NUNIT; u += NW2) {
                if (u < Sk) {
                    float v = sc * arc_pass((const uint2*)d_arcs, d_base[u], d_base[u + 1],
                                            aC, eC, lane);
                    aN[u * 32 + lane] = v;
                    psum += v;
                } else if (t + 1 < Tk) {
                    ex_tile((u - Sk) >> 1, (u - Sk) & 1, t + 1, (t + 1) & 1, x, tw, lane);
                }
            }
        }

        if (mkpart && (stateBlk || !simple)) {
            s_part[wid * 32 + lane] = psum;
            __syncthreads();
            if (wid == 0) {
                float cs4 = 0.0f;
                #pragma unroll
                for (int k = 0; k < 32; k++) cs4 += s_part[k * 32 + lane];
                d_part[blk * 32 + lane] = cs4;
            }
        }

        gbar(g, nblk, tid);
        cur ^= 1;
    }

    // ---- final reduction: objf = mean_b (logC_b + log colsum_b) ----
    if (blk == 0 && wid == 0) {
        float cs = 0.0f;
        for (int r = 0; r < npart; r++) cs += __ldcg(&d_part[r * 32 + lane]);
        double tot = logC + log((double)cs);
        #pragma unroll
        for (int off = 16; off; off >>= 1)
            tot += __shfl_down_sync(0xFFFFFFFFu, tot, off);
        if (lane == 0) out[0] = (float)(tot / (double)Bk);
    }
}

// ================================== launcher =====================================
extern "C" void kernel_launch(void* const* d_in, const int* in_sizes, int n_in,
                              void* d_out, int out_size) {
    const float* x    = (const float*)d_in[0];
    const float* ltp  = (const float*)d_in[1];
    const float* init = (const float*)d_in[2];
    const int*   src  = (const int*)d_in[3];
    const int*   dst  = (const int*)d_in[4];
    const int*   pdf  = (const int*)d_in[5];
    float* out = (float*)d_out;

    int nblk = 0;
    cudaDeviceGetAttribute(&nblk, cudaDevAttrMultiProcessorCount, 0);
    if (nblk <= 0 || nblk > MAXBLK) nblk = 148;

    k_hist<<<NCH, 256>>>(dst);
    k_mid<<<nblk, 256>>>(nblk);
    k_scatter<<<NCH, 128>>>(src, dst, pdf, ltp);
    k_main<<<nblk, 1024>>>(x, init, out, nblk);
}